// round 12
// baseline (speedup 1.0000x reference)
#include <cuda_runtime.h>
#include <math.h>
#include <stdint.h>

#define BB 16
#define TT 2048
#define EE 64
#define HS 16
#define NQT (TT / 128)    // 16 query tiles
#define NKP 4             // max 512-key supertiles per query tile
#define NPAIR4 40         // sum_{jt=0..15} (jt/4 + 1)

// log2(e) * hs^-0.5
#define QSCALE 0.360673760222241f
// fp16 1.0 packed twice (ones B-fragment for l = P*1 row sums)
#define ONE2 0x3C003C00u

// scratch
__device__ float g_q[BB * TT * HS];
__device__ float g_k[BB * TT * HS];
__device__ float g_v[BB * TT * HS];
__device__ float g_rope[TT * HS];
// partials: acc as 4 coalesced float4 fields, plus l (scalar; no-max domain)
__device__ float4 g_part4[BB * NQT * NKP * 4 * 128];
__device__ float g_l[BB * NQT * NKP * 128];

// ---- helpers ----
__device__ __forceinline__ float ex2f(float x) {
    float y; asm("ex2.approx.f32 %0,%1;" : "=f"(y) : "f"(x)); return y;
}
// first operand -> HIGH half, second -> LOW half
__device__ __forceinline__ uint32_t cvt_f16x2(float hi, float lo) {
    uint32_t d; asm("cvt.rn.f16x2.f32 %0,%1,%2;" : "=r"(d) : "f"(hi), "f"(lo)); return d;
}
__device__ __forceinline__ void mma_f16(float c[4],
    uint32_t a0, uint32_t a1, uint32_t a2, uint32_t a3, uint32_t b0, uint32_t b1) {
    asm volatile(
        "mma.sync.aligned.m16n8k16.row.col.f32.f16.f16.f32 "
        "{%0,%1,%2,%3},{%4,%5,%6,%7},{%8,%9},{%0,%1,%2,%3};"
        : "+f"(c[0]), "+f"(c[1]), "+f"(c[2]), "+f"(c[3])
        : "r"(a0), "r"(a1), "r"(a2), "r"(a3), "r"(b0), "r"(b1));
}

// ---------------------------------------------------------------------------
// Kernel 0: RoPE cos/sin table
// ---------------------------------------------------------------------------
__global__ __launch_bounds__(128) void rope_table_kernel()
{
    int idx = blockIdx.x * 128 + threadIdx.x;
    int t = idx >> 3;
    int i = idx & 7;
    float inv = powf(10000.0f, -(float)i * (2.0f / (float)HS));
    float sn, cs;
    sincosf((float)t * inv, &sn, &cs);
    g_rope[t * 16 + 2 * i]     = cs;
    g_rope[t * 16 + 2 * i + 1] = sn;
}

// ---------------------------------------------------------------------------
// Kernel 1: fused QKV projection + RoPE. One thread per (row, half).
// ---------------------------------------------------------------------------
__global__ __launch_bounds__(128) void qkv_rope_kernel(
    const float* __restrict__ x,
    const float* __restrict__ wq,
    const float* __restrict__ wk,
    const float* __restrict__ wv)
{
    __shared__ float swq[EE * 8];
    __shared__ float swk[EE * 8];
    __shared__ float swv[EE * 8];

    int tid = threadIdx.x;
    int half = blockIdx.y;
    int hbase = half * 8;

    for (int i = tid; i < EE * 8; i += 128) {
        int e = i >> 3, h = i & 7;
        swq[i] = wq[e * HS + hbase + h];
        swk[i] = wk[e * HS + hbase + h];
        swv[i] = wv[e * HS + hbase + h];
    }
    __syncthreads();

    int row = blockIdx.x * 128 + tid;
    int t = row & (TT - 1);

    const float4* xr = reinterpret_cast<const float4*>(x + (size_t)row * EE);

    float q[8], k[8], v[8];
#pragma unroll
    for (int h = 0; h < 8; h++) { q[h] = 0.f; k[h] = 0.f; v[h] = 0.f; }

#pragma unroll
    for (int e4 = 0; e4 < EE / 4; e4++) {
        float4 xv = xr[e4];
        float xs[4] = {xv.x, xv.y, xv.z, xv.w};
#pragma unroll
        for (int j = 0; j < 4; j++) {
            int e = e4 * 4 + j;
#pragma unroll
            for (int h = 0; h < 8; h++) {
                q[h] = fmaf(xs[j], swq[e * 8 + h], q[h]);
                k[h] = fmaf(xs[j], swk[e * 8 + h], k[h]);
                v[h] = fmaf(xs[j], swv[e * 8 + h], v[h]);
            }
        }
    }

    const float4* rp = reinterpret_cast<const float4*>(g_rope + t * 16 + hbase);
    float rope[8];
    {
        float4 r0 = rp[0], r1 = rp[1];
        rope[0] = r0.x; rope[1] = r0.y; rope[2] = r0.z; rope[3] = r0.w;
        rope[4] = r1.x; rope[5] = r1.y; rope[6] = r1.z; rope[7] = r1.w;
    }

    float qo[8], ko[8];
#pragma unroll
    for (int i = 0; i < 4; i++) {
        float cs = rope[2 * i], sn = rope[2 * i + 1];
        float qe = q[2 * i], qd = q[2 * i + 1];
        float ke = k[2 * i], kd = k[2 * i + 1];
        qo[2 * i]     = qe * cs - qd * sn;
        qo[2 * i + 1] = qe * sn + qd * cs;
        ko[2 * i]     = ke * cs - kd * sn;
        ko[2 * i + 1] = ke * sn + kd * cs;
    }

    float4* Q4 = reinterpret_cast<float4*>(g_q + (size_t)row * HS + hbase);
    float4* K4 = reinterpret_cast<float4*>(g_k + (size_t)row * HS + hbase);
    float4* V4 = reinterpret_cast<float4*>(g_v + (size_t)row * HS + hbase);
    Q4[0] = make_float4(qo[0], qo[1], qo[2], qo[3]);
    Q4[1] = make_float4(qo[4], qo[5], qo[6], qo[7]);
    K4[0] = make_float4(ko[0], ko[1], ko[2], ko[3]);
    K4[1] = make_float4(ko[4], ko[5], ko[6], ko[7]);
    V4[0] = make_float4(v[0], v[1], v[2], v[3]);
    V4[1] = make_float4(v[4], v[5], v[6], v[7]);
}

// ---------------------------------------------------------------------------
// Kernel 2: tensor-core flash attention partial, no-max softmax
// (scores bounded; 2^-shift cancels in acc/l). l computed by ones-mma.
// One block per (b, jt, 512-key supertile). 4 warps x 32 queries.
// ---------------------------------------------------------------------------
template <bool DIAG>
__device__ __forceinline__ void attn_body(
    int b, int jt, int kp,
    const uint2 (*sK)[32], const uint2 (*sV)[2][32],
    float (*sOut)[17], float* sL)
{
    int tid = threadIdx.x;
    int w = tid >> 5;
    int lane = tid & 31;
    int g = lane >> 2;
    int t4 = lane & 3;
    int st = kp * 512;
    int qwbase = jt * 128 + w * 32;

    // ---- load Q fragments (fp16, scaled by QSCALE) ----
    uint32_t qA[2][4];
#pragma unroll
    for (int mt = 0; mt < 2; mt++) {
        int r0 = qwbase + 16 * mt + g;
        const float* Q0 = g_q + ((size_t)b * TT + r0) * HS;
        const float* Q1 = g_q + ((size_t)b * TT + r0 + 8) * HS;
        float2 f00 = *reinterpret_cast<const float2*>(Q0 + 2 * t4);
        float2 f01 = *reinterpret_cast<const float2*>(Q0 + 2 * t4 + 8);
        float2 f10 = *reinterpret_cast<const float2*>(Q1 + 2 * t4);
        float2 f11 = *reinterpret_cast<const float2*>(Q1 + 2 * t4 + 8);
        qA[mt][0] = cvt_f16x2(f00.y * QSCALE, f00.x * QSCALE);
        qA[mt][1] = cvt_f16x2(f10.y * QSCALE, f10.x * QSCALE);
        qA[mt][2] = cvt_f16x2(f01.y * QSCALE, f01.x * QSCALE);
        qA[mt][3] = cvt_f16x2(f11.y * QSCALE, f11.x * QSCALE);
    }

    // acc[mt][hn][4]: PV accumulators; lacc[mt][4]: l row-sums (c0 = row g, c2 = row g+8)
    float acc[2][2][4], lacc[2][4];
#pragma unroll
    for (int mt = 0; mt < 2; mt++) {
#pragma unroll
        for (int r = 0; r < 4; r++) lacc[mt][r] = 0.f;
#pragma unroll
        for (int hn = 0; hn < 2; hn++)
#pragma unroll
            for (int r = 0; r < 4; r++) acc[mt][hn][r] = 0.f;
    }

    int nchunks = 16;
    if (DIAG) {
        int qmaxw = qwbase + 31;
        nchunks = ((qmaxw - st) >> 5) + 1;
        if (nchunks > 16) nchunks = 16;
    }

    for (int c = 0; c < nchunks; c++) {
        // ---- QK^T: 4 n-tiles x 2 m-tiles, 1 fp16 mma each ----
        float s[4][2][4];
#pragma unroll
        for (int ntl = 0; ntl < 4; ntl++) {
            int nt = c * 4 + ntl;
            uint2 kf = sK[nt][lane];
#pragma unroll
            for (int mt = 0; mt < 2; mt++) {
                s[ntl][mt][0] = 0.f; s[ntl][mt][1] = 0.f;
                s[ntl][mt][2] = 0.f; s[ntl][mt][3] = 0.f;
                mma_f16(s[ntl][mt], qA[mt][0], qA[mt][1], qA[mt][2], qA[mt][3], kf.x, kf.y);
            }
        }

        if (DIAG) {
#pragma unroll
            for (int ntl = 0; ntl < 4; ntl++) {
                int kb = st + (c * 4 + ntl) * 8 + 2 * t4;
#pragma unroll
                for (int mt = 0; mt < 2; mt++) {
                    int r0 = qwbase + 16 * mt + g;
                    if (kb     > r0)     s[ntl][mt][0] = -1e30f;
                    if (kb + 1 > r0)     s[ntl][mt][1] = -1e30f;
                    if (kb     > r0 + 8) s[ntl][mt][2] = -1e30f;
                    if (kb + 1 > r0 + 8) s[ntl][mt][3] = -1e30f;
                }
            }
        }

        // ---- P = ex2(s); shift-free (normalization cancels the scale) ----
        uint32_t pa[2][2][4];   // [ks][mt][reg]
#pragma unroll
        for (int ntl = 0; ntl < 4; ntl++) {
            int ks = ntl >> 1;
            int halfn = ntl & 1;
#pragma unroll
            for (int mt = 0; mt < 2; mt++) {
                float p0 = ex2f(s[ntl][mt][0]);
                float p1 = ex2f(s[ntl][mt][1]);
                float p2 = ex2f(s[ntl][mt][2]);
                float p3 = ex2f(s[ntl][mt][3]);
                pa[ks][mt][0 + 2 * halfn] = cvt_f16x2(p1, p0);
                pa[ks][mt][1 + 2 * halfn] = cvt_f16x2(p3, p2);
            }
        }

        // ---- PV + l: per (ks, mt): 2 hs-tiles of PV + 1 ones-mma for l ----
#pragma unroll
        for (int ks = 0; ks < 2; ks++) {
            int kstep = c * 2 + ks;
#pragma unroll
            for (int hn = 0; hn < 2; hn++) {
                uint2 vf = sV[kstep][hn][lane];
#pragma unroll
                for (int mt = 0; mt < 2; mt++)
                    mma_f16(acc[mt][hn], pa[ks][mt][0], pa[ks][mt][1], pa[ks][mt][2], pa[ks][mt][3], vf.x, vf.y);
            }
#pragma unroll
            for (int mt = 0; mt < 2; mt++)
                mma_f16(lacc[mt], pa[ks][mt][0], pa[ks][mt][1], pa[ks][mt][2], pa[ks][mt][3], ONE2, ONE2);
        }
    }

    // lacc already holds full row sums (mma sums all 16 k per step) -> no shfl

    // ---- epilog via smem transpose ----
#pragma unroll
    for (int mt = 0; mt < 2; mt++) {
        int rl = w * 32 + 16 * mt + g;
#pragma unroll
        for (int hn = 0; hn < 2; hn++) {
            int d = hn * 8 + 2 * t4;
            sOut[rl][d]         = acc[mt][hn][0];
            sOut[rl][d + 1]     = acc[mt][hn][1];
            sOut[rl + 8][d]     = acc[mt][hn][2];
            sOut[rl + 8][d + 1] = acc[mt][hn][3];
        }
        if (t4 == 0) {
            sL[rl]     = lacc[mt][0];
            sL[rl + 8] = lacc[mt][2];
        }
    }
    __syncthreads();

    size_t pb = ((size_t)(b * NQT + jt) * NKP + kp);
    float4* dst = g_part4 + pb * 4 * 128 + tid;
#pragma unroll
    for (int h = 0; h < 4; h++)
        dst[h * 128] = make_float4(sOut[tid][4 * h], sOut[tid][4 * h + 1],
                                   sOut[tid][4 * h + 2], sOut[tid][4 * h + 3]);
    g_l[pb * 128 + tid] = sL[tid];
}

__global__ __launch_bounds__(128) void attn_part_kernel()
{
    __shared__ uint2 sK[64][32];       // 64 n-tiles x 8 keys, fp16 frags
    __shared__ uint2 sV[32][2][32];    // 32 ksteps x 2 hs-tiles, fp16 frags
    __shared__ float sOut[128][17];
    __shared__ float sL[128];

    int b = blockIdx.y;
    int p = blockIdx.x;
    int jt = 0, rem = p;
    while (rem >= (jt >> 2) + 1) { rem -= (jt >> 2) + 1; jt++; }
    int kp = rem;
    int st = kp * 512;
    int tid = threadIdx.x;

    // ---- prolog: pack K fragments ----
    for (int idx = tid; idx < 64 * 32; idx += 128) {
        int nt = idx >> 5, ln = idx & 31;
        int key = st + nt * 8 + (ln >> 2);
        int d0 = 2 * (ln & 3);
        const float* Kr = g_k + ((size_t)b * TT + key) * HS;
        float2 k0 = *reinterpret_cast<const float2*>(Kr + d0);
        float2 k1 = *reinterpret_cast<const float2*>(Kr + d0 + 8);
        sK[nt][ln] = make_uint2(cvt_f16x2(k0.y, k0.x), cvt_f16x2(k1.y, k1.x));
    }

    // ---- prolog: pack V fragments ----
    for (int idx = tid; idx < 32 * 2 * 32; idx += 128) {
        int ks = idx >> 6, rest = idx & 63;
        int hn = rest >> 5, ln = rest & 31;
        int dim = hn * 8 + (ln >> 2);
        int key0 = st + ks * 16 + 2 * (ln & 3);
        const float* Vb = g_v + (size_t)b * TT * HS + dim;
        float v0 = Vb[(size_t)key0 * HS];
        float v1 = Vb[(size_t)(key0 + 1) * HS];
        float v2 = Vb[(size_t)(key0 + 8) * HS];
        float v3 = Vb[(size_t)(key0 + 9) * HS];
        sV[ks][hn][ln] = make_uint2(cvt_f16x2(v1, v0), cvt_f16x2(v3, v2));
    }
    __syncthreads();

    if (kp == (jt >> 2))
        attn_body<true>(b, jt, kp, sK, sV, sOut, sL);
    else
        attn_body<false>(b, jt, kp, sK, sV, sOut, sL);
}

// ---------------------------------------------------------------------------
// Kernel 3: combine partials: plain sums (no-max domain). n <= 4.
// ---------------------------------------------------------------------------
__global__ __launch_bounds__(128) void combine_kernel(float* __restrict__ out)
{
    int jt = blockIdx.x;
    int b  = blockIdx.y;
    int tid = threadIdx.x;
    int n = (jt >> 2) + 1;

    const float4* base = g_part4 + (size_t)(b * NQT + jt) * NKP * 4 * 128 + tid;
    const float*  lb   = g_l     + (size_t)(b * NQT + jt) * NKP * 128 + tid;

    float acc[HS];
#pragma unroll
    for (int h = 0; h < HS; h++) acc[h] = 0.f;
    float l_tot = 0.f;

#pragma unroll 2
    for (int i = 0; i < n; i++) {
        const float4* pp = base + (size_t)i * 4 * 128;
        float4 a0 = pp[0];
        float4 a1 = pp[128];
        float4 a2 = pp[256];
        float4 a3 = pp[384];
        l_tot += lb[i * 128];
        acc[0]  += a0.x; acc[1]  += a0.y; acc[2]  += a0.z; acc[3]  += a0.w;
        acc[4]  += a1.x; acc[5]  += a1.y; acc[6]  += a1.z; acc[7]  += a1.w;
        acc[8]  += a2.x; acc[9]  += a2.y; acc[10] += a2.z; acc[11] += a2.w;
        acc[12] += a3.x; acc[13] += a3.y; acc[14] += a3.z; acc[15] += a3.w;
    }

    float inv_l = 1.0f / l_tot;
    int t = jt * 128 + tid;
    float4* Or = reinterpret_cast<float4*>(out + ((size_t)b * TT + t) * HS);
#pragma unroll
    for (int j = 0; j < 4; j++)
        Or[j] = make_float4(acc[4 * j] * inv_l, acc[4 * j + 1] * inv_l,
                            acc[4 * j + 2] * inv_l, acc[4 * j + 3] * inv_l);
}

extern "C" void kernel_launch(void* const* d_in, const int* in_sizes, int n_in,
                              void* d_out, int out_size)
{
    const float* x  = (const float*)d_in[0];
    const float* wq = (const float*)d_in[1];
    const float* wk = (const float*)d_in[2];
    const float* wv = (const float*)d_in[3];
    float* out = (float*)d_out;

    rope_table_kernel<<<(TT * 8) / 128, 128>>>();

    dim3 grid_q(256, 2);
    qkv_rope_kernel<<<grid_q, 128>>>(x, wq, wk, wv);

    dim3 grid_p(NPAIR4, BB);
    attn_part_kernel<<<grid_p, 128>>>();

    dim3 grid_c(NQT, BB);
    combine_kernel<<<grid_c, 128>>>(out);
}

// round 13
// speedup vs baseline: 1.1125x; 1.1125x over previous
#include <cuda_runtime.h>
#include <cuda_fp16.h>
#include <math.h>
#include <stdint.h>

#define BB 16
#define TT 2048
#define EE 64
#define HS 16
#define NQT (TT / 128)    // 16 query tiles
#define NKP 4             // max 512-key supertiles per query tile
#define NPAIR4 40         // sum_{jt=0..15} (jt/4 + 1)

// log2(e) * hs^-0.5
#define QSCALE 0.360673760222241f

// scratch
__device__ float g_q[BB * TT * HS];
__device__ float g_k[BB * TT * HS];
__device__ float g_v[BB * TT * HS];
__device__ float g_rope[TT * HS];
// partials: acc as 4 coalesced float4 fields, plus l (scalar; shift-free domain)
__device__ float4 g_part4[BB * NQT * NKP * 4 * 128];
__device__ float g_l[BB * NQT * NKP * 128];

// ---- helpers ----
__device__ __forceinline__ float ex2f(float x) {
    float y; asm("ex2.approx.f32 %0,%1;" : "=f"(y) : "f"(x)); return y;
}
// first operand -> HIGH half, second -> LOW half
__device__ __forceinline__ uint32_t cvt_f16x2(float hi, float lo) {
    uint32_t d; asm("cvt.rn.f16x2.f32 %0,%1,%2;" : "=r"(d) : "f"(hi), "f"(lo)); return d;
}
__device__ __forceinline__ uint32_t hadd2u(uint32_t a, uint32_t b) {
    __half2 r = __hadd2(*reinterpret_cast<__half2*>(&a), *reinterpret_cast<__half2*>(&b));
    return *reinterpret_cast<uint32_t*>(&r);
}
__device__ __forceinline__ uint32_t ex2h2(uint32_t x) {
    __half2 r = h2exp2(*reinterpret_cast<__half2*>(&x));
    return *reinterpret_cast<uint32_t*>(&r);
}
__device__ __forceinline__ float2 h22f2(uint32_t h) {
    return __half22float2(*reinterpret_cast<__half2*>(&h));
}
// fp32-accumulator fp16 mma (PV)
__device__ __forceinline__ void mma_f16(float c[4],
    uint32_t a0, uint32_t a1, uint32_t a2, uint32_t a3, uint32_t b0, uint32_t b1) {
    asm volatile(
        "mma.sync.aligned.m16n8k16.row.col.f32.f16.f16.f32 "
        "{%0,%1,%2,%3},{%4,%5,%6,%7},{%8,%9},{%0,%1,%2,%3};"
        : "+f"(c[0]), "+f"(c[1]), "+f"(c[2]), "+f"(c[3])
        : "r"(a0), "r"(a1), "r"(a2), "r"(a3), "r"(b0), "r"(b1));
}
// fp16-accumulator fp16 mma (QK^T); C = 0
__device__ __forceinline__ void mma_f16acc(uint32_t& d0, uint32_t& d1,
    uint32_t a0, uint32_t a1, uint32_t a2, uint32_t a3, uint32_t b0, uint32_t b1) {
    asm volatile(
        "mma.sync.aligned.m16n8k16.row.col.f16.f16.f16.f16 "
        "{%0,%1},{%2,%3,%4,%5},{%6,%7},{%8,%9};"
        : "=r"(d0), "=r"(d1)
        : "r"(a0), "r"(a1), "r"(a2), "r"(a3), "r"(b0), "r"(b1), "r"(0u), "r"(0u));
}

// ---------------------------------------------------------------------------
// Kernel 0: RoPE cos/sin table
// ---------------------------------------------------------------------------
__global__ __launch_bounds__(128) void rope_table_kernel()
{
    int idx = blockIdx.x * 128 + threadIdx.x;
    int t = idx >> 3;
    int i = idx & 7;
    float inv = powf(10000.0f, -(float)i * (2.0f / (float)HS));
    float sn, cs;
    sincosf((float)t * inv, &sn, &cs);
    g_rope[t * 16 + 2 * i]     = cs;
    g_rope[t * 16 + 2 * i + 1] = sn;
}

// ---------------------------------------------------------------------------
// Kernel 1: fused QKV projection + RoPE. One thread per (row, half).
// ---------------------------------------------------------------------------
__global__ __launch_bounds__(128) void qkv_rope_kernel(
    const float* __restrict__ x,
    const float* __restrict__ wq,
    const float* __restrict__ wk,
    const float* __restrict__ wv)
{
    __shared__ float swq[EE * 8];
    __shared__ float swk[EE * 8];
    __shared__ float swv[EE * 8];

    int tid = threadIdx.x;
    int half = blockIdx.y;
    int hbase = half * 8;

    for (int i = tid; i < EE * 8; i += 128) {
        int e = i >> 3, h = i & 7;
        swq[i] = wq[e * HS + hbase + h];
        swk[i] = wk[e * HS + hbase + h];
        swv[i] = wv[e * HS + hbase + h];
    }
    __syncthreads();

    int row = blockIdx.x * 128 + tid;
    int t = row & (TT - 1);

    const float4* xr = reinterpret_cast<const float4*>(x + (size_t)row * EE);

    float q[8], k[8], v[8];
#pragma unroll
    for (int h = 0; h < 8; h++) { q[h] = 0.f; k[h] = 0.f; v[h] = 0.f; }

#pragma unroll
    for (int e4 = 0; e4 < EE / 4; e4++) {
        float4 xv = xr[e4];
        float xs[4] = {xv.x, xv.y, xv.z, xv.w};
#pragma unroll
        for (int j = 0; j < 4; j++) {
            int e = e4 * 4 + j;
#pragma unroll
            for (int h = 0; h < 8; h++) {
                q[h] = fmaf(xs[j], swq[e * 8 + h], q[h]);
                k[h] = fmaf(xs[j], swk[e * 8 + h], k[h]);
                v[h] = fmaf(xs[j], swv[e * 8 + h], v[h]);
            }
        }
    }

    const float4* rp = reinterpret_cast<const float4*>(g_rope + t * 16 + hbase);
    float rope[8];
    {
        float4 r0 = rp[0], r1 = rp[1];
        rope[0] = r0.x; rope[1] = r0.y; rope[2] = r0.z; rope[3] = r0.w;
        rope[4] = r1.x; rope[5] = r1.y; rope[6] = r1.z; rope[7] = r1.w;
    }

    float qo[8], ko[8];
#pragma unroll
    for (int i = 0; i < 4; i++) {
        float cs = rope[2 * i], sn = rope[2 * i + 1];
        float qe = q[2 * i], qd = q[2 * i + 1];
        float ke = k[2 * i], kd = k[2 * i + 1];
        qo[2 * i]     = qe * cs - qd * sn;
        qo[2 * i + 1] = qe * sn + qd * cs;
        ko[2 * i]     = ke * cs - kd * sn;
        ko[2 * i + 1] = ke * sn + kd * cs;
    }

    float4* Q4 = reinterpret_cast<float4*>(g_q + (size_t)row * HS + hbase);
    float4* K4 = reinterpret_cast<float4*>(g_k + (size_t)row * HS + hbase);
    float4* V4 = reinterpret_cast<float4*>(g_v + (size_t)row * HS + hbase);
    Q4[0] = make_float4(qo[0], qo[1], qo[2], qo[3]);
    Q4[1] = make_float4(qo[4], qo[5], qo[6], qo[7]);
    K4[0] = make_float4(ko[0], ko[1], ko[2], ko[3]);
    K4[1] = make_float4(ko[4], ko[5], ko[6], ko[7]);
    V4[0] = make_float4(v[0], v[1], v[2], v[3]);
    V4[1] = make_float4(v[4], v[5], v[6], v[7]);
}

// ---------------------------------------------------------------------------
// Kernel 2: tensor-core flash attention partial.
// QK^T with fp16 accumulators: D-fragment packing == PV A-fragment packing,
// so softmax is h2exp2 in place. Shift-free (scores bounded, scale cancels).
// One block per (b, jt, 512-key supertile). 4 warps x 32 queries.
// ---------------------------------------------------------------------------
template <bool DIAG>
__device__ __forceinline__ void attn_body(
    int b, int jt, int kp,
    const uint2 (*sK)[32], const uint2 (*sV)[2][32],
    float (*sOut)[17], float* sL)
{
    int tid = threadIdx.x;
    int w = tid >> 5;
    int lane = tid & 31;
    int g = lane >> 2;
    int t4 = lane & 3;
    int st = kp * 512;
    int qwbase = jt * 128 + w * 32;

    // ---- load Q fragments (fp16, scaled by QSCALE) ----
    uint32_t qA[2][4];
#pragma unroll
    for (int mt = 0; mt < 2; mt++) {
        int r0 = qwbase + 16 * mt + g;
        const float* Q0 = g_q + ((size_t)b * TT + r0) * HS;
        const float* Q1 = g_q + ((size_t)b * TT + r0 + 8) * HS;
        float2 f00 = *reinterpret_cast<const float2*>(Q0 + 2 * t4);
        float2 f01 = *reinterpret_cast<const float2*>(Q0 + 2 * t4 + 8);
        float2 f10 = *reinterpret_cast<const float2*>(Q1 + 2 * t4);
        float2 f11 = *reinterpret_cast<const float2*>(Q1 + 2 * t4 + 8);
        qA[mt][0] = cvt_f16x2(f00.y * QSCALE, f00.x * QSCALE);
        qA[mt][1] = cvt_f16x2(f10.y * QSCALE, f10.x * QSCALE);
        qA[mt][2] = cvt_f16x2(f01.y * QSCALE, f01.x * QSCALE);
        qA[mt][3] = cvt_f16x2(f11.y * QSCALE, f11.x * QSCALE);
    }

    float l[4], acc[2][2][4];
#pragma unroll
    for (int r = 0; r < 4; r++) l[r] = 0.f;
#pragma unroll
    for (int mt = 0; mt < 2; mt++)
#pragma unroll
        for (int hn = 0; hn < 2; hn++)
#pragma unroll
            for (int r = 0; r < 4; r++) acc[mt][hn][r] = 0.f;

    int nchunks = 16;
    if (DIAG) {
        int qmaxw = qwbase + 31;
        nchunks = ((qmaxw - st) >> 5) + 1;
        if (nchunks > 16) nchunks = 16;
    }

    for (int c = 0; c < nchunks; c++) {
        // ---- QK^T (f16 accum) + in-place packed softmax ----
        uint32_t pa[2][2][4];        // [ks][mt][reg] fp16x2 P fragments
        uint32_t lp[2][2];           // packed l partials [mt][row01]
        lp[0][0] = 0u; lp[0][1] = 0u; lp[1][0] = 0u; lp[1][1] = 0u;

#pragma unroll
        for (int ntl = 0; ntl < 4; ntl++) {
            int nt = c * 4 + ntl;
            uint2 kf = sK[nt][lane];
            int ks = ntl >> 1;
            int halfn = ntl & 1;
#pragma unroll
            for (int mt = 0; mt < 2; mt++) {
                uint32_t d0, d1;
                mma_f16acc(d0, d1, qA[mt][0], qA[mt][1], qA[mt][2], qA[mt][3], kf.x, kf.y);
                if (DIAG) {
                    int kb = st + nt * 8 + 2 * t4;
                    int r0 = qwbase + 16 * mt + g;
                    uint32_t b0 = ((kb > r0)     ? 0x0000FC00u : 0u) |
                                  ((kb + 1 > r0) ? 0xFC000000u : 0u);
                    uint32_t b1 = ((kb > r0 + 8)     ? 0x0000FC00u : 0u) |
                                  ((kb + 1 > r0 + 8) ? 0xFC000000u : 0u);
                    d0 = hadd2u(d0, b0);
                    d1 = hadd2u(d1, b1);
                }
                uint32_t p0 = ex2h2(d0);   // row g,  keys (2t4, 2t4+1)
                uint32_t p1 = ex2h2(d1);   // row g+8
                pa[ks][mt][0 + 2 * halfn] = p0;
                pa[ks][mt][1 + 2 * halfn] = p1;
                lp[mt][0] = hadd2u(lp[mt][0], p0);
                lp[mt][1] = hadd2u(lp[mt][1], p1);
            }
        }

        // ---- flush packed l partials to f32 ----
#pragma unroll
        for (int mt = 0; mt < 2; mt++) {
            float2 f0 = h22f2(lp[mt][0]);
            float2 f1 = h22f2(lp[mt][1]);
            l[mt * 2]     += f0.x + f0.y;
            l[mt * 2 + 1] += f1.x + f1.y;
        }

        // ---- PV: 2 ksteps x 2 hs-tiles x 2 m-tiles, f32-accum fp16 mma ----
#pragma unroll
        for (int ks = 0; ks < 2; ks++) {
            int kstep = c * 2 + ks;
#pragma unroll
            for (int hn = 0; hn < 2; hn++) {
                uint2 vf = sV[kstep][hn][lane];
#pragma unroll
                for (int mt = 0; mt < 2; mt++)
                    mma_f16(acc[mt][hn], pa[ks][mt][0], pa[ks][mt][1], pa[ks][mt][2], pa[ks][mt][3], vf.x, vf.y);
            }
        }
    }

    // ---- reduce l across the 4-thread group (once per supertile) ----
#pragma unroll
    for (int r = 0; r < 4; r++) {
        l[r] += __shfl_xor_sync(0xffffffffu, l[r], 1);
        l[r] += __shfl_xor_sync(0xffffffffu, l[r], 2);
    }

    // ---- epilog via smem transpose ----
#pragma unroll
    for (int mt = 0; mt < 2; mt++) {
        int rl = w * 32 + 16 * mt + g;
#pragma unroll
        for (int hn = 0; hn < 2; hn++) {
            int d = hn * 8 + 2 * t4;
            sOut[rl][d]         = acc[mt][hn][0];
            sOut[rl][d + 1]     = acc[mt][hn][1];
            sOut[rl + 8][d]     = acc[mt][hn][2];
            sOut[rl + 8][d + 1] = acc[mt][hn][3];
        }
        if (t4 == 0) {
            sL[rl]     = l[mt * 2];
            sL[rl + 8] = l[mt * 2 + 1];
        }
    }
    __syncthreads();

    size_t pb = ((size_t)(b * NQT + jt) * NKP + kp);
    float4* dst = g_part4 + pb * 4 * 128 + tid;
#pragma unroll
    for (int h = 0; h < 4; h++)
        dst[h * 128] = make_float4(sOut[tid][4 * h], sOut[tid][4 * h + 1],
                                   sOut[tid][4 * h + 2], sOut[tid][4 * h + 3]);
    g_l[pb * 128 + tid] = sL[tid];
}

__global__ __launch_bounds__(128) void attn_part_kernel()
{
    __shared__ uint2 sK[64][32];       // 64 n-tiles x 8 keys, fp16 frags
    __shared__ uint2 sV[32][2][32];    // 32 ksteps x 2 hs-tiles, fp16 frags
    __shared__ float sOut[128][17];
    __shared__ float sL[128];

    int b = blockIdx.y;
    int p = blockIdx.x;
    int jt = 0, rem = p;
    while (rem >= (jt >> 2) + 1) { rem -= (jt >> 2) + 1; jt++; }
    int kp = rem;
    int st = kp * 512;
    int tid = threadIdx.x;

    // ---- prolog: pack K fragments ----
    for (int idx = tid; idx < 64 * 32; idx += 128) {
        int nt = idx >> 5, ln = idx & 31;
        int key = st + nt * 8 + (ln >> 2);
        int d0 = 2 * (ln & 3);
        const float* Kr = g_k + ((size_t)b * TT + key) * HS;
        float2 k0 = *reinterpret_cast<const float2*>(Kr + d0);
        float2 k1 = *reinterpret_cast<const float2*>(Kr + d0 + 8);
        sK[nt][ln] = make_uint2(cvt_f16x2(k0.y, k0.x), cvt_f16x2(k1.y, k1.x));
    }

    // ---- prolog: pack V fragments ----
    for (int idx = tid; idx < 32 * 2 * 32; idx += 128) {
        int ks = idx >> 6, rest = idx & 63;
        int hn = rest >> 5, ln = rest & 31;
        int dim = hn * 8 + (ln >> 2);
        int key0 = st + ks * 16 + 2 * (ln & 3);
        const float* Vb = g_v + (size_t)b * TT * HS + dim;
        float v0 = Vb[(size_t)key0 * HS];
        float v1 = Vb[(size_t)(key0 + 1) * HS];
        float v2 = Vb[(size_t)(key0 + 8) * HS];
        float v3 = Vb[(size_t)(key0 + 9) * HS];
        sV[ks][hn][ln] = make_uint2(cvt_f16x2(v1, v0), cvt_f16x2(v3, v2));
    }
    __syncthreads();

    if (kp == (jt >> 2))
        attn_body<true>(b, jt, kp, sK, sV, sOut, sL);
    else
        attn_body<false>(b, jt, kp, sK, sV, sOut, sL);
}

// ---------------------------------------------------------------------------
// Kernel 3: combine partials: plain sums (shift-free domain). n <= 4.
// ---------------------------------------------------------------------------
__global__ __launch_bounds__(128) void combine_kernel(float* __restrict__ out)
{
    int jt = blockIdx.x;
    int b  = blockIdx.y;
    int tid = threadIdx.x;
    int n = (jt >> 2) + 1;

    const float4* base = g_part4 + (size_t)(b * NQT + jt) * NKP * 4 * 128 + tid;
    const float*  lb   = g_l     + (size_t)(b * NQT + jt) * NKP * 128 + tid;

    float acc[HS];
#pragma unroll
    for (int h = 0; h < HS; h++) acc[h] = 0.f;
    float l_tot = 0.f;

#pragma unroll 2
    for (int i = 0; i < n; i++) {
        const float4* pp = base + (size_t)i * 4 * 128;
        float4 a0 = pp[0];
        float4 a1 = pp[128];
        float4 a2 = pp[256];
        float4 a3 = pp[384];
        l_tot += lb[i * 128];
        acc[0]  += a0.x; acc[1]  += a0.y; acc[2]  += a0.z; acc[3]  += a0.w;
        acc[4]  += a1.x; acc[5]  += a1.y; acc[6]  += a1.z; acc[7]  += a1.w;
        acc[8]  += a2.x; acc[9]  += a2.y; acc[10] += a2.z; acc[11] += a2.w;
        acc[12] += a3.x; acc[13] += a3.y; acc[14] += a3.z; acc[15] += a3.w;
    }

    float inv_l = 1.0f / l_tot;
    int t = jt * 128 + tid;
    float4* Or = reinterpret_cast<float4*>(out + ((size_t)b * TT + t) * HS);
#pragma unroll
    for (int j = 0; j < 4; j++)
        Or[j] = make_float4(acc[4 * j] * inv_l, acc[4 * j + 1] * inv_l,
                            acc[4 * j + 2] * inv_l, acc[4 * j + 3] * inv_l);
}

extern "C" void kernel_launch(void* const* d_in, const int* in_sizes, int n_in,
                              void* d_out, int out_size)
{
    const float* x  = (const float*)d_in[0];
    const float* wq = (const float*)d_in[1];
    const float* wk = (const float*)d_in[2];
    const float* wv = (const float*)d_in[3];
    float* out = (float*)d_out;

    rope_table_kernel<<<(TT * 8) / 128, 128>>>();

    dim3 grid_q(256, 2);
    qkv_rope_kernel<<<grid_q, 128>>>(x, wq, wk, wv);

    dim3 grid_p(NPAIR4, BB);
    attn_part_kernel<<<grid_p, 128>>>();

    dim3 grid_c(NQT, BB);
    combine_kernel<<<grid_c, 128>>>(out);
}

// round 14
// speedup vs baseline: 1.2035x; 1.0818x over previous
#include <cuda_runtime.h>
#include <cuda_fp16.h>
#include <math.h>
#include <stdint.h>

#define BB 16
#define TT 2048
#define EE 64
#define HS 16
#define NQT (TT / 128)    // 16 query tiles
#define NKP 4             // max 512-key supertiles per query tile
#define NPAIR4 40         // sum_{jt=0..15} (jt/4 + 1)

// log2(e) * hs^-0.5
#define QSCALE 0.360673760222241f

// scratch
__device__ float g_q[BB * TT * HS];
__device__ float g_k[BB * TT * HS];
__device__ float g_v[BB * TT * HS];
__device__ float g_rope[TT * HS];
// partials: acc as 4 coalesced float4 fields, plus l (scalar; shift-free domain)
__device__ float4 g_part4[BB * NQT * NKP * 4 * 128];
__device__ float g_l[BB * NQT * NKP * 128];

// ---- helpers ----
// first operand -> HIGH half, second -> LOW half
__device__ __forceinline__ uint32_t cvt_f16x2(float hi, float lo) {
    uint32_t d; asm("cvt.rn.f16x2.f32 %0,%1,%2;" : "=r"(d) : "f"(hi), "f"(lo)); return d;
}
__device__ __forceinline__ uint32_t hadd2u(uint32_t a, uint32_t b) {
    __half2 r = __hadd2(*reinterpret_cast<__half2*>(&a), *reinterpret_cast<__half2*>(&b));
    return *reinterpret_cast<uint32_t*>(&r);
}
__device__ __forceinline__ uint32_t ex2h2(uint32_t x) {
    __half2 r = h2exp2(*reinterpret_cast<__half2*>(&x));
    return *reinterpret_cast<uint32_t*>(&r);
}
__device__ __forceinline__ float2 h22f2(uint32_t h) {
    return __half22float2(*reinterpret_cast<__half2*>(&h));
}
// fp32-accumulator fp16 mma (PV)
__device__ __forceinline__ void mma_f16(float c[4],
    uint32_t a0, uint32_t a1, uint32_t a2, uint32_t a3, uint32_t b0, uint32_t b1) {
    asm volatile(
        "mma.sync.aligned.m16n8k16.row.col.f32.f16.f16.f32 "
        "{%0,%1,%2,%3},{%4,%5,%6,%7},{%8,%9},{%0,%1,%2,%3};"
        : "+f"(c[0]), "+f"(c[1]), "+f"(c[2]), "+f"(c[3])
        : "r"(a0), "r"(a1), "r"(a2), "r"(a3), "r"(b0), "r"(b1));
}
// fp16-accumulator fp16 mma (QK^T); C = 0
__device__ __forceinline__ void mma_f16acc(uint32_t& d0, uint32_t& d1,
    uint32_t a0, uint32_t a1, uint32_t a2, uint32_t a3, uint32_t b0, uint32_t b1) {
    asm volatile(
        "mma.sync.aligned.m16n8k16.row.col.f16.f16.f16.f16 "
        "{%0,%1},{%2,%3,%4,%5},{%6,%7},{%8,%9};"
        : "=r"(d0), "=r"(d1)
        : "r"(a0), "r"(a1), "r"(a2), "r"(a3), "r"(b0), "r"(b1), "r"(0u), "r"(0u));
}

// ---------------------------------------------------------------------------
// Kernel 0: RoPE cos/sin table
// ---------------------------------------------------------------------------
__global__ __launch_bounds__(128) void rope_table_kernel()
{
    int idx = blockIdx.x * 128 + threadIdx.x;
    int t = idx >> 3;
    int i = idx & 7;
    float inv = powf(10000.0f, -(float)i * (2.0f / (float)HS));
    float sn, cs;
    sincosf((float)t * inv, &sn, &cs);
    g_rope[t * 16 + 2 * i]     = cs;
    g_rope[t * 16 + 2 * i + 1] = sn;
}

// ---------------------------------------------------------------------------
// Kernel 1: fused QKV projection + RoPE. One thread per (row, half).
// ---------------------------------------------------------------------------
__global__ __launch_bounds__(128) void qkv_rope_kernel(
    const float* __restrict__ x,
    const float* __restrict__ wq,
    const float* __restrict__ wk,
    const float* __restrict__ wv)
{
    __shared__ float swq[EE * 8];
    __shared__ float swk[EE * 8];
    __shared__ float swv[EE * 8];

    int tid = threadIdx.x;
    int half = blockIdx.y;
    int hbase = half * 8;

    for (int i = tid; i < EE * 8; i += 128) {
        int e = i >> 3, h = i & 7;
        swq[i] = wq[e * HS + hbase + h];
        swk[i] = wk[e * HS + hbase + h];
        swv[i] = wv[e * HS + hbase + h];
    }
    __syncthreads();

    int row = blockIdx.x * 128 + tid;
    int t = row & (TT - 1);

    const float4* xr = reinterpret_cast<const float4*>(x + (size_t)row * EE);

    float q[8], k[8], v[8];
#pragma unroll
    for (int h = 0; h < 8; h++) { q[h] = 0.f; k[h] = 0.f; v[h] = 0.f; }

#pragma unroll
    for (int e4 = 0; e4 < EE / 4; e4++) {
        float4 xv = xr[e4];
        float xs[4] = {xv.x, xv.y, xv.z, xv.w};
#pragma unroll
        for (int j = 0; j < 4; j++) {
            int e = e4 * 4 + j;
#pragma unroll
            for (int h = 0; h < 8; h++) {
                q[h] = fmaf(xs[j], swq[e * 8 + h], q[h]);
                k[h] = fmaf(xs[j], swk[e * 8 + h], k[h]);
                v[h] = fmaf(xs[j], swv[e * 8 + h], v[h]);
            }
        }
    }

    const float4* rp = reinterpret_cast<const float4*>(g_rope + t * 16 + hbase);
    float rope[8];
    {
        float4 r0 = rp[0], r1 = rp[1];
        rope[0] = r0.x; rope[1] = r0.y; rope[2] = r0.z; rope[3] = r0.w;
        rope[4] = r1.x; rope[5] = r1.y; rope[6] = r1.z; rope[7] = r1.w;
    }

    float qo[8], ko[8];
#pragma unroll
    for (int i = 0; i < 4; i++) {
        float cs = rope[2 * i], sn = rope[2 * i + 1];
        float qe = q[2 * i], qd = q[2 * i + 1];
        float ke = k[2 * i], kd = k[2 * i + 1];
        qo[2 * i]     = qe * cs - qd * sn;
        qo[2 * i + 1] = qe * sn + qd * cs;
        ko[2 * i]     = ke * cs - kd * sn;
        ko[2 * i + 1] = ke * sn + kd * cs;
    }

    float4* Q4 = reinterpret_cast<float4*>(g_q + (size_t)row * HS + hbase);
    float4* K4 = reinterpret_cast<float4*>(g_k + (size_t)row * HS + hbase);
    float4* V4 = reinterpret_cast<float4*>(g_v + (size_t)row * HS + hbase);
    Q4[0] = make_float4(qo[0], qo[1], qo[2], qo[3]);
    Q4[1] = make_float4(qo[4], qo[5], qo[6], qo[7]);
    K4[0] = make_float4(ko[0], ko[1], ko[2], ko[3]);
    K4[1] = make_float4(ko[4], ko[5], ko[6], ko[7]);
    V4[0] = make_float4(v[0], v[1], v[2], v[3]);
    V4[1] = make_float4(v[4], v[5], v[6], v[7]);
}

// ---------------------------------------------------------------------------
// Kernel 2: tensor-core flash attention partial.
// 8 warps x 16 queries (256 threads): 2x warp parallelism per SMSP vs the
// 4-warp layout, halving the exposed QKmma->ex2->PVmma dependency chain.
// One block per (b, jt, 512-key supertile).
// ---------------------------------------------------------------------------
template <bool DIAG>
__device__ __forceinline__ void attn_body(
    int b, int jt, int kp,
    const uint2 (*sK)[32], const uint2 (*sV)[2][32],
    float (*sOut)[17], float* sL)
{
    int tid = threadIdx.x;
    int w = tid >> 5;          // 0..7
    int lane = tid & 31;
    int g = lane >> 2;
    int t4 = lane & 3;
    int st = kp * 512;
    int qwbase = jt * 128 + w * 16;   // 16 query rows per warp

    // ---- load Q fragments (fp16, scaled by QSCALE) ----
    uint32_t qA[4];
    {
        int r0 = qwbase + g;
        const float* Q0 = g_q + ((size_t)b * TT + r0) * HS;
        const float* Q1 = g_q + ((size_t)b * TT + r0 + 8) * HS;
        float2 f00 = *reinterpret_cast<const float2*>(Q0 + 2 * t4);
        float2 f01 = *reinterpret_cast<const float2*>(Q0 + 2 * t4 + 8);
        float2 f10 = *reinterpret_cast<const float2*>(Q1 + 2 * t4);
        float2 f11 = *reinterpret_cast<const float2*>(Q1 + 2 * t4 + 8);
        qA[0] = cvt_f16x2(f00.y * QSCALE, f00.x * QSCALE);
        qA[1] = cvt_f16x2(f10.y * QSCALE, f10.x * QSCALE);
        qA[2] = cvt_f16x2(f01.y * QSCALE, f01.x * QSCALE);
        qA[3] = cvt_f16x2(f11.y * QSCALE, f11.x * QSCALE);
    }

    float l[2], acc[2][4];
    l[0] = 0.f; l[1] = 0.f;
#pragma unroll
    for (int hn = 0; hn < 2; hn++)
#pragma unroll
        for (int r = 0; r < 4; r++) acc[hn][r] = 0.f;

    int nchunks = 16;
    if (DIAG) {
        int qmaxw = qwbase + 15;
        nchunks = ((qmaxw - st) >> 5) + 1;
        if (nchunks > 16) nchunks = 16;
    }

    for (int c = 0; c < nchunks; c++) {
        // ---- QK^T (f16 accum) + in-place packed softmax ----
        uint32_t pa[2][4];   // [ks][reg] fp16x2 P fragments
        uint32_t lp0 = 0u, lp1 = 0u;

#pragma unroll
        for (int ntl = 0; ntl < 4; ntl++) {
            int nt = c * 4 + ntl;
            uint2 kf = sK[nt][lane];
            int ks = ntl >> 1;
            int halfn = ntl & 1;
            uint32_t d0, d1;
            mma_f16acc(d0, d1, qA[0], qA[1], qA[2], qA[3], kf.x, kf.y);
            if (DIAG) {
                int kb = st + nt * 8 + 2 * t4;
                int r0 = qwbase + g;
                uint32_t b0 = ((kb > r0)     ? 0x0000FC00u : 0u) |
                              ((kb + 1 > r0) ? 0xFC000000u : 0u);
                uint32_t b1 = ((kb > r0 + 8)     ? 0x0000FC00u : 0u) |
                              ((kb + 1 > r0 + 8) ? 0xFC000000u : 0u);
                d0 = hadd2u(d0, b0);
                d1 = hadd2u(d1, b1);
            }
            uint32_t p0 = ex2h2(d0);   // row g,  keys (2t4, 2t4+1)
            uint32_t p1 = ex2h2(d1);   // row g+8
            pa[ks][0 + 2 * halfn] = p0;
            pa[ks][1 + 2 * halfn] = p1;
            lp0 = hadd2u(lp0, p0);
            lp1 = hadd2u(lp1, p1);
        }

        // ---- flush packed l partials to f32 ----
        {
            float2 f0 = h22f2(lp0);
            float2 f1 = h22f2(lp1);
            l[0] += f0.x + f0.y;
            l[1] += f1.x + f1.y;
        }

        // ---- PV: 2 ksteps x 2 hs-tiles, f32-accum fp16 mma ----
#pragma unroll
        for (int ks = 0; ks < 2; ks++) {
            int kstep = c * 2 + ks;
#pragma unroll
            for (int hn = 0; hn < 2; hn++) {
                uint2 vf = sV[kstep][hn][lane];
                mma_f16(acc[hn], pa[ks][0], pa[ks][1], pa[ks][2], pa[ks][3], vf.x, vf.y);
            }
        }
    }

    // ---- reduce l across the 4-thread group ----
#pragma unroll
    for (int r = 0; r < 2; r++) {
        l[r] += __shfl_xor_sync(0xffffffffu, l[r], 1);
        l[r] += __shfl_xor_sync(0xffffffffu, l[r], 2);
    }

    // ---- epilog via smem transpose ----
    {
        int rl = w * 16 + g;
#pragma unroll
        for (int hn = 0; hn < 2; hn++) {
            int d = hn * 8 + 2 * t4;
            sOut[rl][d]         = acc[hn][0];
            sOut[rl][d + 1]     = acc[hn][1];
            sOut[rl + 8][d]     = acc[hn][2];
            sOut[rl + 8][d + 1] = acc[hn][3];
        }
        if (t4 == 0) {
            sL[rl]     = l[0];
            sL[rl + 8] = l[1];
        }
    }
    __syncthreads();

    size_t pb = ((size_t)(b * NQT + jt) * NKP + kp);
    if (tid < 128) {
        float4* dst = g_part4 + pb * 4 * 128 + tid;
#pragma unroll
        for (int h = 0; h < 4; h++)
            dst[h * 128] = make_float4(sOut[tid][4 * h], sOut[tid][4 * h + 1],
                                       sOut[tid][4 * h + 2], sOut[tid][4 * h + 3]);
        g_l[pb * 128 + tid] = sL[tid];
    }
}

__global__ __launch_bounds__(256) void attn_part_kernel()
{
    __shared__ uint2 sK[64][32];       // 64 n-tiles x 8 keys, fp16 frags
    __shared__ uint2 sV[32][2][32];    // 32 ksteps x 2 hs-tiles, fp16 frags
    __shared__ float sOut[128][17];
    __shared__ float sL[128];

    int b = blockIdx.y;
    int p = blockIdx.x;
    int jt = 0, rem = p;
    while (rem >= (jt >> 2) + 1) { rem -= (jt >> 2) + 1; jt++; }
    int kp = rem;
    int st = kp * 512;
    int tid = threadIdx.x;

    // ---- prolog: pack K fragments ----
    for (int idx = tid; idx < 64 * 32; idx += 256) {
        int nt = idx >> 5, ln = idx & 31;
        int key = st + nt * 8 + (ln >> 2);
        int d0 = 2 * (ln & 3);
        const float* Kr = g_k + ((size_t)b * TT + key) * HS;
        float2 k0 = *reinterpret_cast<const float2*>(Kr + d0);
        float2 k1 = *reinterpret_cast<const float2*>(Kr + d0 + 8);
        sK[nt][ln] = make_uint2(cvt_f16x2(k0.y, k0.x), cvt_f16x2(k1.y, k1.x));
    }

    // ---- prolog: pack V fragments ----
    for (int idx = tid; idx < 32 * 2 * 32; idx += 256) {
        int ks = idx >> 6, rest = idx & 63;
        int hn = rest >> 5, ln = rest & 31;
        int dim = hn * 8 + (ln >> 2);
        int key0 = st + ks * 16 + 2 * (ln & 3);
        const float* Vb = g_v + (size_t)b * TT * HS + dim;
        float v0 = Vb[(size_t)key0 * HS];
        float v1 = Vb[(size_t)(key0 + 1) * HS];
        float v2 = Vb[(size_t)(key0 + 8) * HS];
        float v3 = Vb[(size_t)(key0 + 9) * HS];
        sV[ks][hn][ln] = make_uint2(cvt_f16x2(v1, v0), cvt_f16x2(v3, v2));
    }
    __syncthreads();

    if (kp == (jt >> 2))
        attn_body<true>(b, jt, kp, sK, sV, sOut, sL);
    else
        attn_body<false>(b, jt, kp, sK, sV, sOut, sL);
}

// ---------------------------------------------------------------------------
// Kernel 3: combine partials. 512 threads: one per (query, float4-field).
// All n<=4 partials loaded predicated-unrolled for MLP.
// ---------------------------------------------------------------------------
__global__ __launch_bounds__(512) void combine_kernel(float* __restrict__ out)
{
    int jt = blockIdx.x;
    int b  = blockIdx.y;
    int tid = threadIdx.x;
    int q = tid >> 2;        // query row within tile
    int h = tid & 3;         // float4 field
    int n = (jt >> 2) + 1;

    size_t pb0 = (size_t)(b * NQT + jt) * NKP;
    const float4* base = g_part4 + pb0 * 4 * 128 + h * 128 + q;
    const float*  lb   = g_l     + pb0 * 128 + q;

    float4 av[NKP];
    float  lv[NKP];
#pragma unroll
    for (int i = 0; i < NKP; i++) {
        if (i < n) {
            av[i] = base[(size_t)i * 4 * 128];
            lv[i] = lb[(size_t)i * 128];
        } else {
            av[i] = make_float4(0.f, 0.f, 0.f, 0.f);
            lv[i] = 0.f;
        }
    }

    float4 a = av[0];
    float l_tot = lv[0];
#pragma unroll
    for (int i = 1; i < NKP; i++) {
        a.x += av[i].x; a.y += av[i].y; a.z += av[i].z; a.w += av[i].w;
        l_tot += lv[i];
    }

    float inv_l = 1.0f / l_tot;
    int t = jt * 128 + q;
    float4* Or = reinterpret_cast<float4*>(out + ((size_t)b * TT + t) * HS);
    Or[h] = make_float4(a.x * inv_l, a.y * inv_l, a.z * inv_l, a.w * inv_l);
}

extern "C" void kernel_launch(void* const* d_in, const int* in_sizes, int n_in,
                              void* d_out, int out_size)
{
    const float* x  = (const float*)d_in[0];
    const float* wq = (const float*)d_in[1];
    const float* wk = (const float*)d_in[2];
    const float* wv = (const float*)d_in[3];
    float* out = (float*)d_out;

    rope_table_kernel<<<(TT * 8) / 128, 128>>>();

    dim3 grid_q(256, 2);
    qkv_rope_kernel<<<grid_q, 128>>>(x, wq, wk, wv);

    dim3 grid_p(NPAIR4, BB);
    attn_part_kernel<<<grid_p, 256>>>();

    dim3 grid_c(NQT, BB);
    combine_kernel<<<grid_c, 512>>>(out);
}

// round 15
// speedup vs baseline: 1.2214x; 1.0149x over previous
#include <cuda_runtime.h>
#include <cuda_fp16.h>
#include <math.h>
#include <stdint.h>

#define BB 16
#define TT 2048
#define EE 64
#define HS 16
#define NQT (TT / 128)    // 16 query tiles
#define NKP 4             // max 512-key supertiles per query tile
#define NPAIR4 40         // sum_{jt=0..15} (jt/4 + 1)

// log2(e) * hs^-0.5
#define QSCALE 0.360673760222241f

// scratch
__device__ float g_q[BB * TT * HS];
__device__ float g_k[BB * TT * HS];
__device__ float g_v[BB * TT * HS];
__device__ float g_rope[TT * HS];
// pre-packed fp16 mma fragments
__device__ uint2 g_kf[BB * 256 * 32];        // [b][nt=key/8][lane]
__device__ uint2 g_vf[BB * 128 * 2 * 32];    // [b][ks=key/16][hn][lane]
// partials: acc as 4 coalesced float4 fields, plus l (scalar; shift-free domain)
__device__ float4 g_part4[BB * NQT * NKP * 4 * 128];
__device__ float g_l[BB * NQT * NKP * 128];

// ---- helpers ----
// first operand -> HIGH half, second -> LOW half
__device__ __forceinline__ uint32_t cvt_f16x2(float hi, float lo) {
    uint32_t d; asm("cvt.rn.f16x2.f32 %0,%1,%2;" : "=r"(d) : "f"(hi), "f"(lo)); return d;
}
__device__ __forceinline__ uint32_t hadd2u(uint32_t a, uint32_t b) {
    __half2 r = __hadd2(*reinterpret_cast<__half2*>(&a), *reinterpret_cast<__half2*>(&b));
    return *reinterpret_cast<uint32_t*>(&r);
}
__device__ __forceinline__ uint32_t ex2h2(uint32_t x) {
    __half2 r = h2exp2(*reinterpret_cast<__half2*>(&x));
    return *reinterpret_cast<uint32_t*>(&r);
}
__device__ __forceinline__ float2 h22f2(uint32_t h) {
    return __half22float2(*reinterpret_cast<__half2*>(&h));
}
// fp32-accumulator fp16 mma (PV)
__device__ __forceinline__ void mma_f16(float c[4],
    uint32_t a0, uint32_t a1, uint32_t a2, uint32_t a3, uint32_t b0, uint32_t b1) {
    asm volatile(
        "mma.sync.aligned.m16n8k16.row.col.f32.f16.f16.f32 "
        "{%0,%1,%2,%3},{%4,%5,%6,%7},{%8,%9},{%0,%1,%2,%3};"
        : "+f"(c[0]), "+f"(c[1]), "+f"(c[2]), "+f"(c[3])
        : "r"(a0), "r"(a1), "r"(a2), "r"(a3), "r"(b0), "r"(b1));
}
// fp16-accumulator fp16 mma (QK^T); C = 0
__device__ __forceinline__ void mma_f16acc(uint32_t& d0, uint32_t& d1,
    uint32_t a0, uint32_t a1, uint32_t a2, uint32_t a3, uint32_t b0, uint32_t b1) {
    asm volatile(
        "mma.sync.aligned.m16n8k16.row.col.f16.f16.f16.f16 "
        "{%0,%1},{%2,%3,%4,%5},{%6,%7},{%8,%9};"
        : "=r"(d0), "=r"(d1)
        : "r"(a0), "r"(a1), "r"(a2), "r"(a3), "r"(b0), "r"(b1), "r"(0u), "r"(0u));
}

// ---------------------------------------------------------------------------
// Kernel 0: RoPE cos/sin table
// ---------------------------------------------------------------------------
__global__ __launch_bounds__(128) void rope_table_kernel()
{
    int idx = blockIdx.x * 128 + threadIdx.x;
    int t = idx >> 3;
    int i = idx & 7;
    float inv = powf(10000.0f, -(float)i * (2.0f / (float)HS));
    float sn, cs;
    sincosf((float)t * inv, &sn, &cs);
    g_rope[t * 16 + 2 * i]     = cs;
    g_rope[t * 16 + 2 * i + 1] = sn;
}

// ---------------------------------------------------------------------------
// Kernel 1: fused QKV projection + RoPE. One thread per (row, half).
// ---------------------------------------------------------------------------
__global__ __launch_bounds__(128) void qkv_rope_kernel(
    const float* __restrict__ x,
    const float* __restrict__ wq,
    const float* __restrict__ wk,
    const float* __restrict__ wv)
{
    __shared__ float swq[EE * 8];
    __shared__ float swk[EE * 8];
    __shared__ float swv[EE * 8];

    int tid = threadIdx.x;
    int half = blockIdx.y;
    int hbase = half * 8;

    for (int i = tid; i < EE * 8; i += 128) {
        int e = i >> 3, h = i & 7;
        swq[i] = wq[e * HS + hbase + h];
        swk[i] = wk[e * HS + hbase + h];
        swv[i] = wv[e * HS + hbase + h];
    }
    __syncthreads();

    int row = blockIdx.x * 128 + tid;
    int t = row & (TT - 1);

    const float4* xr = reinterpret_cast<const float4*>(x + (size_t)row * EE);

    float q[8], k[8], v[8];
#pragma unroll
    for (int h = 0; h < 8; h++) { q[h] = 0.f; k[h] = 0.f; v[h] = 0.f; }

#pragma unroll
    for (int e4 = 0; e4 < EE / 4; e4++) {
        float4 xv = xr[e4];
        float xs[4] = {xv.x, xv.y, xv.z, xv.w};
#pragma unroll
        for (int j = 0; j < 4; j++) {
            int e = e4 * 4 + j;
#pragma unroll
            for (int h = 0; h < 8; h++) {
                q[h] = fmaf(xs[j], swq[e * 8 + h], q[h]);
                k[h] = fmaf(xs[j], swk[e * 8 + h], k[h]);
                v[h] = fmaf(xs[j], swv[e * 8 + h], v[h]);
            }
        }
    }

    const float4* rp = reinterpret_cast<const float4*>(g_rope + t * 16 + hbase);
    float rope[8];
    {
        float4 r0 = rp[0], r1 = rp[1];
        rope[0] = r0.x; rope[1] = r0.y; rope[2] = r0.z; rope[3] = r0.w;
        rope[4] = r1.x; rope[5] = r1.y; rope[6] = r1.z; rope[7] = r1.w;
    }

    float qo[8], ko[8];
#pragma unroll
    for (int i = 0; i < 4; i++) {
        float cs = rope[2 * i], sn = rope[2 * i + 1];
        float qe = q[2 * i], qd = q[2 * i + 1];
        float ke = k[2 * i], kd = k[2 * i + 1];
        qo[2 * i]     = qe * cs - qd * sn;
        qo[2 * i + 1] = qe * sn + qd * cs;
        ko[2 * i]     = ke * cs - kd * sn;
        ko[2 * i + 1] = ke * sn + kd * cs;
    }

    float4* Q4 = reinterpret_cast<float4*>(g_q + (size_t)row * HS + hbase);
    float4* K4 = reinterpret_cast<float4*>(g_k + (size_t)row * HS + hbase);
    float4* V4 = reinterpret_cast<float4*>(g_v + (size_t)row * HS + hbase);
    Q4[0] = make_float4(qo[0], qo[1], qo[2], qo[3]);
    Q4[1] = make_float4(qo[4], qo[5], qo[6], qo[7]);
    K4[0] = make_float4(ko[0], ko[1], ko[2], ko[3]);
    K4[1] = make_float4(ko[4], ko[5], ko[6], ko[7]);
    V4[0] = make_float4(v[0], v[1], v[2], v[3]);
    V4[1] = make_float4(v[4], v[5], v[6], v[7]);
}

// ---------------------------------------------------------------------------
// Kernel 1b: pack K and V into fp16 mma-fragment layout, ONCE per batch.
// K entries: idx < BB*256*32; V entries follow.
// ---------------------------------------------------------------------------
__global__ __launch_bounds__(128) void pack_kv_kernel()
{
    int idx = blockIdx.x * 128 + threadIdx.x;
    const int NKE = BB * 256 * 32;   // 131072

    if (idx < NKE) {
        int b   = idx >> 13;          // 256*32 = 8192
        int rem = idx & 8191;
        int nt  = rem >> 5;
        int ln  = rem & 31;
        int key = nt * 8 + (ln >> 2);
        int d0  = 2 * (ln & 3);
        const float* Kr = g_k + ((size_t)b * TT + key) * HS;
        float2 k0 = *reinterpret_cast<const float2*>(Kr + d0);
        float2 k1 = *reinterpret_cast<const float2*>(Kr + d0 + 8);
        g_kf[idx] = make_uint2(cvt_f16x2(k0.y, k0.x), cvt_f16x2(k1.y, k1.x));
    } else {
        int e   = idx - NKE;
        int b   = e >> 13;            // 128*2*32 = 8192
        int rem = e & 8191;
        int ks  = rem >> 6;
        int rest = rem & 63;
        int hn  = rest >> 5;
        int ln  = rest & 31;
        int dim = hn * 8 + (ln >> 2);
        int key0 = ks * 16 + 2 * (ln & 3);
        const float* Vb = g_v + (size_t)b * TT * HS + dim;
        float v0 = Vb[(size_t)key0 * HS];
        float v1 = Vb[(size_t)(key0 + 1) * HS];
        float v2 = Vb[(size_t)(key0 + 8) * HS];
        float v3 = Vb[(size_t)(key0 + 9) * HS];
        g_vf[e] = make_uint2(cvt_f16x2(v1, v0), cvt_f16x2(v3, v2));
    }
}

// ---------------------------------------------------------------------------
// Kernel 2: tensor-core flash attention partial.
// 8 warps x 16 queries (256 threads). No K/V smem: fragments read directly
// from pre-packed global (coalesced LDG.64, L1/L2 resident).
// One block per (b, jt, 512-key supertile).
// ---------------------------------------------------------------------------
template <bool DIAG>
__device__ __forceinline__ void attn_body(
    int b, int jt, int kp,
    float (*sOut)[17], float* sL)
{
    int tid = threadIdx.x;
    int w = tid >> 5;          // 0..7
    int lane = tid & 31;
    int g = lane >> 2;
    int t4 = lane & 3;
    int st = kp * 512;
    int qwbase = jt * 128 + w * 16;   // 16 query rows per warp

    const uint2* Kf = g_kf + ((size_t)b * 256 + kp * 64) * 32 + lane;
    const uint2* Vf = g_vf + (((size_t)b * 128 + kp * 32) * 2) * 32 + lane;

    // ---- load Q fragments (fp16, scaled by QSCALE) ----
    uint32_t qA[4];
    {
        int r0 = qwbase + g;
        const float* Q0 = g_q + ((size_t)b * TT + r0) * HS;
        const float* Q1 = g_q + ((size_t)b * TT + r0 + 8) * HS;
        float2 f00 = *reinterpret_cast<const float2*>(Q0 + 2 * t4);
        float2 f01 = *reinterpret_cast<const float2*>(Q0 + 2 * t4 + 8);
        float2 f10 = *reinterpret_cast<const float2*>(Q1 + 2 * t4);
        float2 f11 = *reinterpret_cast<const float2*>(Q1 + 2 * t4 + 8);
        qA[0] = cvt_f16x2(f00.y * QSCALE, f00.x * QSCALE);
        qA[1] = cvt_f16x2(f10.y * QSCALE, f10.x * QSCALE);
        qA[2] = cvt_f16x2(f01.y * QSCALE, f01.x * QSCALE);
        qA[3] = cvt_f16x2(f11.y * QSCALE, f11.x * QSCALE);
    }

    float l[2], acc[2][4];
    l[0] = 0.f; l[1] = 0.f;
#pragma unroll
    for (int hn = 0; hn < 2; hn++)
#pragma unroll
        for (int r = 0; r < 4; r++) acc[hn][r] = 0.f;

    int nchunks = 16;
    if (DIAG) {
        int qmaxw = qwbase + 15;
        nchunks = ((qmaxw - st) >> 5) + 1;
        if (nchunks > 16) nchunks = 16;
    }

    for (int c = 0; c < nchunks; c++) {
        // ---- QK^T (f16 accum) + in-place packed softmax ----
        uint32_t pa[2][4];   // [ks][reg] fp16x2 P fragments
        uint32_t lp0 = 0u, lp1 = 0u;

        // prefetch K fragments for the whole chunk (4 loads in flight)
        uint2 kf[4];
#pragma unroll
        for (int ntl = 0; ntl < 4; ntl++)
            kf[ntl] = Kf[(size_t)(c * 4 + ntl) * 32];
        // prefetch V fragments too
        uint2 vf[2][2];
#pragma unroll
        for (int ks = 0; ks < 2; ks++)
#pragma unroll
            for (int hn = 0; hn < 2; hn++)
                vf[ks][hn] = Vf[(size_t)((c * 2 + ks) * 2 + hn) * 32];

#pragma unroll
        for (int ntl = 0; ntl < 4; ntl++) {
            int nt = c * 4 + ntl;
            int ks = ntl >> 1;
            int halfn = ntl & 1;
            uint32_t d0, d1;
            mma_f16acc(d0, d1, qA[0], qA[1], qA[2], qA[3], kf[ntl].x, kf[ntl].y);
            if (DIAG) {
                int kb = st + nt * 8 + 2 * t4;
                int r0 = qwbase + g;
                uint32_t b0 = ((kb > r0)     ? 0x0000FC00u : 0u) |
                              ((kb + 1 > r0) ? 0xFC000000u : 0u);
                uint32_t b1 = ((kb > r0 + 8)     ? 0x0000FC00u : 0u) |
                              ((kb + 1 > r0 + 8) ? 0xFC000000u : 0u);
                d0 = hadd2u(d0, b0);
                d1 = hadd2u(d1, b1);
            }
            uint32_t p0 = ex2h2(d0);   // row g,  keys (2t4, 2t4+1)
            uint32_t p1 = ex2h2(d1);   // row g+8
            pa[ks][0 + 2 * halfn] = p0;
            pa[ks][1 + 2 * halfn] = p1;
            lp0 = hadd2u(lp0, p0);
            lp1 = hadd2u(lp1, p1);
        }

        // ---- flush packed l partials to f32 ----
        {
            float2 f0 = h22f2(lp0);
            float2 f1 = h22f2(lp1);
            l[0] += f0.x + f0.y;
            l[1] += f1.x + f1.y;
        }

        // ---- PV: 2 ksteps x 2 hs-tiles, f32-accum fp16 mma ----
#pragma unroll
        for (int ks = 0; ks < 2; ks++)
#pragma unroll
            for (int hn = 0; hn < 2; hn++)
                mma_f16(acc[hn], pa[ks][0], pa[ks][1], pa[ks][2], pa[ks][3],
                        vf[ks][hn].x, vf[ks][hn].y);
    }

    // ---- reduce l across the 4-thread group ----
#pragma unroll
    for (int r = 0; r < 2; r++) {
        l[r] += __shfl_xor_sync(0xffffffffu, l[r], 1);
        l[r] += __shfl_xor_sync(0xffffffffu, l[r], 2);
    }

    // ---- epilog via smem transpose ----
    {
        int rl = w * 16 + g;
#pragma unroll
        for (int hn = 0; hn < 2; hn++) {
            int d = hn * 8 + 2 * t4;
            sOut[rl][d]         = acc[hn][0];
            sOut[rl][d + 1]     = acc[hn][1];
            sOut[rl + 8][d]     = acc[hn][2];
            sOut[rl + 8][d + 1] = acc[hn][3];
        }
        if (t4 == 0) {
            sL[rl]     = l[0];
            sL[rl + 8] = l[1];
        }
    }
    __syncthreads();

    size_t pb = ((size_t)(b * NQT + jt) * NKP + kp);
    if (tid < 128) {
        float4* dst = g_part4 + pb * 4 * 128 + tid;
#pragma unroll
        for (int h = 0; h < 4; h++)
            dst[h * 128] = make_float4(sOut[tid][4 * h], sOut[tid][4 * h + 1],
                                       sOut[tid][4 * h + 2], sOut[tid][4 * h + 3]);
        g_l[pb * 128 + tid] = sL[tid];
    }
}

__global__ __launch_bounds__(256) void attn_part_kernel()
{
    __shared__ float sOut[128][17];
    __shared__ float sL[128];

    int b = blockIdx.y;
    int p = blockIdx.x;
    int jt = 0, rem = p;
    while (rem >= (jt >> 2) + 1) { rem -= (jt >> 2) + 1; jt++; }
    int kp = rem;

    if (kp == (jt >> 2))
        attn_body<true>(b, jt, kp, sOut, sL);
    else
        attn_body<false>(b, jt, kp, sOut, sL);
}

// ---------------------------------------------------------------------------
// Kernel 3: combine partials. 512 threads: one per (query, float4-field).
// ---------------------------------------------------------------------------
__global__ __launch_bounds__(512) void combine_kernel(float* __restrict__ out)
{
    int jt = blockIdx.x;
    int b  = blockIdx.y;
    int tid = threadIdx.x;
    int q = tid >> 2;        // query row within tile
    int h = tid & 3;         // float4 field
    int n = (jt >> 2) + 1;

    size_t pb0 = (size_t)(b * NQT + jt) * NKP;
    const float4* base = g_part4 + pb0 * 4 * 128 + h * 128 + q;
    const float*  lb   = g_l     + pb0 * 128 + q;

    float4 av[NKP];
    float  lv[NKP];
#pragma unroll
    for (int i = 0; i < NKP; i++) {
        if (i < n) {
            av[i] = base[(size_t)i * 4 * 128];
            lv[i] = lb[(size_t)i * 128];
        } else {
            av[i] = make_float4(0.f, 0.f, 0.f, 0.f);
            lv[i] = 0.f;
        }
    }

    float4 a = av[0];
    float l_tot = lv[0];
#pragma unroll
    for (int i = 1; i < NKP; i++) {
        a.x += av[i].x; a.y += av[i].y; a.z += av[i].z; a.w += av[i].w;
        l_tot += lv[i];
    }

    float inv_l = 1.0f / l_tot;
    int t = jt * 128 + q;
    float4* Or = reinterpret_cast<float4*>(out + ((size_t)b * TT + t) * HS);
    Or[h] = make_float4(a.x * inv_l, a.y * inv_l, a.z * inv_l, a.w * inv_l);
}

extern "C" void kernel_launch(void* const* d_in, const int* in_sizes, int n_in,
                              void* d_out, int out_size)
{
    const float* x  = (const float*)d_in[0];
    const float* wq = (const float*)d_in[1];
    const float* wk = (const float*)d_in[2];
    const float* wv = (const float*)d_in[3];
    float* out = (float*)d_out;

    rope_table_kernel<<<(TT * 8) / 128, 128>>>();

    dim3 grid_q(256, 2);
    qkv_rope_kernel<<<grid_q, 128>>>(x, wq, wk, wv);

    pack_kv_kernel<<<(2 * BB * 256 * 32) / 128, 128>>>();

    dim3 grid_p(NPAIR4, BB);
    attn_part_kernel<<<grid_p, 256>>>();

    dim3 grid_c(NQT, BB);
    combine_kernel<<<grid_c, 512>>>(out);
}